// round 15
// baseline (speedup 1.0000x reference)
#include <cuda_runtime.h>
#include <cuda_fp16.h>
#include <math.h>

#define HF 200
#define WF 200
#define CH 256
#define HO 7
#define WO 7
#define SUBS 2
#define HS (HO * SUBS)   // 14
#define WS (WO * SUBS)   // 14

#define ROW_BYTES (WF * CH * 2)   // 102400
#define COL_BYTES (CH * 2)        // 512
#define SPITCH 264                // halves per staged position (256 + 8 pad)
#define NTHR 224

#define TCHUNKS 25                // 8 feature rows per chunk
#define BLKS_PER_CHUNK 16         // 8 channel groups x 2 spatial halves
#define TGRID (TCHUNKS * BLKS_PER_CHUNK)   // 400 blocks = one wave

// Channels-last fp16 scratch copy: g_featTh[(y*WF + x)*CH + c]  (20.5 MB)
__device__ __align__(1024) __half g_featTh[HF * WF * CH];
__device__ int g_chunk_cnt[TCHUNKS];   // zero-init; self-reset each launch
__device__ int g_done_cnt;

static __device__ __forceinline__ __half2 u2h2(unsigned u) {
    return *reinterpret_cast<__half2*>(&u);
}
static __device__ __forceinline__ unsigned long long evict_last_policy() {
    unsigned long long pol;
    asm("createpolicy.fractional.L2::evict_last.b64 %0, 1.0;" : "=l"(pol));
    return pol;
}

#define LDG128_NC_EL(r, p, pol)                                                \
    asm volatile("ld.global.nc.L2::cache_hint.v4.u32 {%0,%1,%2,%3}, [%4], %5;" \
                 : "=r"((r)[0]), "=r"((r)[1]), "=r"((r)[2]), "=r"((r)[3])      \
                 : "l"(p), "l"(pol))

// ---------------------------------------------------------------------------
// Kernel 1: transpose, 400 fat blocks (one wave), chunk-progress counters.
// Block b: chunk = b/16 (8 feature rows), q = b%16 -> channel group (q&7),
// spatial half (q>>3). 25 tiles of 32 spatial x 32 channels per block,
// processed 5 at a time with front-batched loads (MLP=20/thread).
// ---------------------------------------------------------------------------
__global__ __launch_bounds__(256) void transpose_kernel(const float* __restrict__ in) {
    cudaTriggerProgrammaticLaunchCompletion();

    __shared__ float tile[5][32][33];
    const int b     = blockIdx.x;
    const int chunk = b >> 4;
    const int q     = b & 15;
    const int c0    = (q & 7) * 32;
    const int tile0 = chunk * 50 + (q >> 3) * 25;

    const int tx  = threadIdx.x;   // 0..31
    const int ty  = threadIdx.y;   // 0..7
    const int tid = ty * 32 + tx;
    const unsigned long long pol = evict_last_policy();

    for (int g = 0; g < 5; g++) {
        // front-batched loads: 5 tiles x 4 rows = 20 independent LDGs
        float v[5][4];
#pragma unroll
        for (int tt = 0; tt < 5; tt++) {
            const int p0 = (tile0 + g * 5 + tt) * 32;
#pragma unroll
            for (int i = 0; i < 4; i++) {
                v[tt][i] = in[(size_t)(c0 + ty + 8 * i) * (HF * WF) + p0 + tx];
            }
        }
#pragma unroll
        for (int tt = 0; tt < 5; tt++) {
#pragma unroll
            for (int i = 0; i < 4; i++) {
                tile[tt][ty + 8 * i][tx] = v[tt][i];
            }
        }
        __syncthreads();
#pragma unroll
        for (int tt = 0; tt < 5; tt++) {
            const int p0 = (tile0 + g * 5 + tt) * 32;
#pragma unroll
            for (int it = 0; it < 2; it++) {
                const int idx = tid + it * 256;
                const int pl  = idx >> 4;
                const int k   = idx & 15;
                __half2 h = __floats2half2_rn(tile[tt][2 * k][pl], tile[tt][2 * k + 1][pl]);
                unsigned hv = *(unsigned*)&h;
                __half* dst = &g_featTh[(size_t)(p0 + pl) * CH + c0 + 2 * k];
                asm volatile("st.global.L2::cache_hint.b32 [%0], %1, %2;"
                             :: "l"(dst), "r"(hv), "l"(pol) : "memory");
            }
        }
        __syncthreads();
    }

    // publish: all 8 rows of this (chunk, cg, half) slice are written
    __threadfence();
    __syncthreads();
    if (tid == 0) atomicAdd(&g_chunk_cnt[chunk], 1);
}

// ---------------------------------------------------------------------------
// Kernel 2: ROI align + 2x2 max subsample (R14 body), launched via PDL at
// t~0; waits only for the <=4 row-chunks it actually reads via counters.
// ---------------------------------------------------------------------------
__global__ __launch_bounds__(NTHR, 3) void roialign_kernel(
    const float* __restrict__ rois,
    const float* __restrict__ img_size,
    float* __restrict__ out)
{
    __shared__ __align__(16) __half s_half[WO * SPITCH];  // 3.7 KB

    const int n   = blockIdx.x;
    const int ph  = blockIdx.y;
    const int tid = threadIdx.x;
    const int pw  = tid >> 5;     // 0..6
    const int c8  = tid & 31;     // 0..31

    // rois/img_size are harness inputs: safe before the producer finishes.
    const float4 roi = __ldg((const float4*)rois + n);
    const float Hi = __ldg(img_size);
    const float Wi = __ldg(img_size + 1);
    const float sy_scale = (HF - 1.0f) / (Hi - 1.0f);
    const float sx_scale = (WF - 1.0f) / (Wi - 1.0f);
    const float r0 = roi.x * sy_scale;
    const float r1 = roi.y * sx_scale;
    const float h_step = (roi.z * sy_scale - r0) * (1.0f / (float)HS);
    const float w_step = (roi.w * sx_scale - r1) * (1.0f / (float)WS);

    const float yy0 = ((float)(2 * ph) + 0.5f) * h_step + r0;
    const float yy1 = yy0 + h_step;
    const float xx0 = ((float)(2 * pw) + 0.5f) * w_step + r1;
    const float xx1 = xx0 + w_step;

    const int iy0 = __float2int_rd(yy0);
    const int iy1 = __float2int_rd(yy1);
    const int ix0 = __float2int_rd(xx0);
    const int ix1 = __float2int_rd(xx1);

    const __half2 fy0 = __float2half2_rn(yy0 - (float)iy0);
    const __half2 fy1 = __float2half2_rn(yy1 - (float)iy1);
    const __half2 fx0 = __float2half2_rn(xx0 - (float)ix0);
    const __half2 fx1 = __float2half2_rn(xx1 - (float)ix1);

    const unsigned ru0 = (unsigned)iy0 * ROW_BYTES;
    const unsigned ru1 = (unsigned)iy1 * ROW_BYTES;
    const unsigned rd0 = ru0 + ROW_BYTES;
    const unsigned rd1 = ru1 + ROW_BYTES;
    const unsigned cl0 = (unsigned)ix0 * COL_BYTES;
    const unsigned cl1 = (unsigned)ix1 * COL_BYTES;
    const unsigned cr0 = cl0 + COL_BYTES;
    const unsigned cr1 = cl1 + COL_BYTES;

    const char* fb = (const char*)g_featTh + c8 * 16;
    const unsigned long long pol = evict_last_policy();

    // writeback indices precomputed in the wait window
    int wc = tid / 7;
    const int wpw = tid - wc * 7;
    float* gp = out + (size_t)n * (CH * HO * WO) + (size_t)wc * (HO * WO)
                    + ph * WO + wpw;

    // --- wait for exactly the row-chunks this block reads ---
    if (tid == 0) {
        const int ca = iy0 >> 3;
        const int cb = (iy0 + 1) >> 3;
        const int cc = iy1 >> 3;
        const int cd = (iy1 + 1) >> 3;
        volatile int* cnt = (volatile int*)g_chunk_cnt;
        while (cnt[ca] < BLKS_PER_CHUNK) __nanosleep(200);
        while (cnt[cb] < BLKS_PER_CHUNK) __nanosleep(200);
        while (cnt[cc] < BLKS_PER_CHUNK) __nanosleep(200);
        while (cnt[cd] < BLKS_PER_CHUNK) __nanosleep(200);
        __threadfence();
    }
    __syncthreads();

    // --- 16 forced LDG.128s: 64 live registers, back-to-back issue ---
    unsigned v[64];
    LDG128_NC_EL(v +  0, fb + (ru0 + cl0), pol);
    LDG128_NC_EL(v +  4, fb + (ru0 + cr0), pol);
    LDG128_NC_EL(v +  8, fb + (rd0 + cl0), pol);
    LDG128_NC_EL(v + 12, fb + (rd0 + cr0), pol);
    LDG128_NC_EL(v + 16, fb + (ru0 + cl1), pol);
    LDG128_NC_EL(v + 20, fb + (ru0 + cr1), pol);
    LDG128_NC_EL(v + 24, fb + (rd0 + cl1), pol);
    LDG128_NC_EL(v + 28, fb + (rd0 + cr1), pol);
    LDG128_NC_EL(v + 32, fb + (ru1 + cl0), pol);
    LDG128_NC_EL(v + 36, fb + (ru1 + cr0), pol);
    LDG128_NC_EL(v + 40, fb + (rd1 + cl0), pol);
    LDG128_NC_EL(v + 44, fb + (rd1 + cr0), pol);
    LDG128_NC_EL(v + 48, fb + (ru1 + cl1), pol);
    LDG128_NC_EL(v + 52, fb + (ru1 + cr1), pol);
    LDG128_NC_EL(v + 56, fb + (rd1 + cl1), pol);
    LDG128_NC_EL(v + 60, fb + (rd1 + cr1), pol);

    __half2 best[4];
    const __half2 ninf = __float2half2_rn(-60000.0f);
#pragma unroll
    for (int j = 0; j < 4; j++) best[j] = ninf;

    const __half2 fxs[4] = {fx0, fx1, fx0, fx1};
    const __half2 fys[4] = {fy0, fy0, fy1, fy1};

#pragma unroll
    for (int s = 0; s < 4; s++) {
        const unsigned* pul = v + s * 16 + 0;
        const unsigned* pur = v + s * 16 + 4;
        const unsigned* pdl = v + s * 16 + 8;
        const unsigned* pdr = v + s * 16 + 12;
        const __half2 fx2 = fxs[s];
        const __half2 fy2 = fys[s];
#pragma unroll
        for (int j = 0; j < 4; j++) {
            const __half2 ul = u2h2(pul[j]);
            const __half2 ur = u2h2(pur[j]);
            const __half2 dl = u2h2(pdl[j]);
            const __half2 dr = u2h2(pdr[j]);
            const __half2 t = __hfma2(fx2, __hsub2(ur, ul), ul);
            const __half2 b = __hfma2(fx2, __hsub2(dr, dl), dl);
            const __half2 vv = __hfma2(fy2, __hsub2(b, t), t);
            best[j] = __hmax2(best[j], vv);
        }
    }

    // --- stage results in fp16 smem ---
    *(uint4*)&s_half[pw * SPITCH + c8 * 8] = *(const uint4*)best;
    __syncthreads();   // all featT reads in this block are complete here

    // done-count + self-reset of counters for the next graph replay
    if (tid == 0) {
        const int total = (int)(gridDim.x * gridDim.y);
        __threadfence();
        const int d = atomicAdd(&g_done_cnt, 1);
        if (d == total - 1) {
#pragma unroll
            for (int i = 0; i < TCHUNKS; i++) g_chunk_cnt[i] = 0;
            __threadfence();
            g_done_cnt = 0;
        }
    }

    // --- writeback: fixed pw per thread, c += 32 per iter ---
    {
        const __half* sp = s_half + wpw * SPITCH;
#pragma unroll
        for (int k = 0; k < 8; k++) {
            *gp = __half2float(sp[wc]);
            wc += 32;
            gp += 32 * (HO * WO);
        }
    }
}

extern "C" void kernel_launch(void* const* d_in, const int* in_sizes, int n_in,
                              void* d_out, int out_size) {
    const float* features = (const float*)d_in[0];  // (1, 256, 200, 200)
    const float* rois     = (const float*)d_in[1];  // (512, 4)
    const float* img_size = (const float*)d_in[2];  // (2,)
    float* out = (float*)d_out;                     // (512, 256, 7, 7)

    const int n_rois = in_sizes[1] / 4;

    dim3 tblock(32, 8);
    transpose_kernel<<<TGRID, tblock>>>(features);

    // PDL launch: secondary becomes launchable once all 400 one-wave
    // transpose blocks have entered (t ~ 0); row-chunk counters gate the
    // actual featT reads per block.
    cudaLaunchConfig_t cfg = {};
    cfg.gridDim  = dim3((unsigned)n_rois, HO, 1);
    cfg.blockDim = dim3(NTHR, 1, 1);
    cfg.dynamicSmemBytes = 0;
    cfg.stream = 0;
    cudaLaunchAttribute attrs[1];
    attrs[0].id = cudaLaunchAttributeProgrammaticStreamSerialization;
    attrs[0].val.programmaticStreamSerializationAllowed = 1;
    cfg.attrs = attrs;
    cfg.numAttrs = 1;
    cudaLaunchKernelEx(&cfg, roialign_kernel, rois, img_size, out);
}

// round 16
// speedup vs baseline: 1.3039x; 1.3039x over previous
#include <cuda_runtime.h>
#include <cuda_fp16.h>
#include <math.h>

#define HF 200
#define WF 200
#define CH 256
#define HO 7
#define WO 7
#define SUBS 2
#define HS (HO * SUBS)   // 14
#define WS (WO * SUBS)   // 14

#define ROW_BYTES (WF * CH * 2)   // 102400
#define COL_BYTES (CH * 2)        // 512
#define SPITCH 264                // halves per staged position (256 + 8 pad)
#define NTHR 224

// Channels-last fp16 scratch copy: g_featTh[(y*WF + x)*CH + c]  (20.5 MB)
__device__ __align__(1024) __half g_featTh[HF * WF * CH];

static __device__ __forceinline__ __half2 u2h2(unsigned u) {
    return *reinterpret_cast<__half2*>(&u);
}
static __device__ __forceinline__ unsigned long long evict_last_policy() {
    unsigned long long pol;
    asm("createpolicy.fractional.L2::evict_last.b64 %0, 1.0;" : "=l"(pol));
    return pol;
}
static __device__ __forceinline__ unsigned long long evict_first_policy() {
    unsigned long long pol;
    asm("createpolicy.fractional.L2::evict_first.b64 %0, 1.0;" : "=l"(pol));
    return pol;
}

// Forced LDG.128 with L2 evict_last hint: asm outputs can't be register-reused
// by ptxas, so 16 in a row issue back-to-back (MLP = 16 guaranteed).
#define LDG128_NC_EL(r, p, pol)                                                \
    asm volatile("ld.global.nc.L2::cache_hint.v4.u32 {%0,%1,%2,%3}, [%4], %5;" \
                 : "=r"((r)[0]), "=r"((r)[1]), "=r"((r)[2]), "=r"((r)[3])      \
                 : "l"(p), "l"(pol))

// ---------------------------------------------------------------------------
// Kernel 1: transpose (C, H*W) f32 -> (H*W, C) fp16.
// f32 reads: evict_first (single-use; keep them from displacing featT).
// featT stores: evict_last (20.5 MB map stays L2-resident for roialign).
// PDL trigger on entry so roialign's prologue overlaps the tail wave.
// ---------------------------------------------------------------------------
__global__ void transpose_kernel(const float* __restrict__ in) {
    cudaTriggerProgrammaticLaunchCompletion();

    __shared__ float tile[32][33];
    const int p0 = blockIdx.x * 32;
    const int c0 = blockIdx.y * 32;
    const int tx = threadIdx.x;
    const int ty = threadIdx.y;

    const unsigned long long pol_ef = evict_first_policy();
#pragma unroll
    for (int i = 0; i < 32; i += 8) {
        const float* src = &in[(size_t)(c0 + ty + i) * (HF * WF) + (p0 + tx)];
        float fv;
        asm volatile("ld.global.nc.L2::cache_hint.f32 %0, [%1], %2;"
                     : "=f"(fv) : "l"(src), "l"(pol_ef));
        tile[ty + i][tx] = fv;
    }
    __syncthreads();

    const unsigned long long pol_el = evict_last_policy();
    const int tid = ty * 32 + tx;
#pragma unroll
    for (int it = 0; it < 2; it++) {
        const int idx = tid + it * 256;
        const int p_local = idx >> 4;
        const int k = idx & 15;
        __half2 h = __floats2half2_rn(tile[2 * k][p_local], tile[2 * k + 1][p_local]);
        unsigned hv = *(unsigned*)&h;
        __half* dst = &g_featTh[(size_t)(p0 + p_local) * CH + c0 + 2 * k];
        asm volatile("st.global.L2::cache_hint.b32 [%0], %1, %2;"
                     :: "l"(dst), "r"(hv), "l"(pol_el) : "memory");
    }
}

// ---------------------------------------------------------------------------
// Kernel 2: ROI align + 2x2 max subsample (R14 body, 24.3us proven).
// Grid: (N, 7). Block: 224 threads = 7 pw x 32 c8.
// PDL: geometry prologue before cudaGridDependencySynchronize();
// 16 forced LDG.128s (MLP=16, evict_last) after; half2 lerp+max;
// fp16 smem staging; division-free coalesced writeback.
// ---------------------------------------------------------------------------
__global__ __launch_bounds__(NTHR, 3) void roialign_kernel(
    const float* __restrict__ rois,
    const float* __restrict__ img_size,
    float* __restrict__ out)
{
    __shared__ __align__(16) __half s_half[WO * SPITCH];  // 3.7 KB

    const int n   = blockIdx.x;
    const int ph  = blockIdx.y;
    const int tid = threadIdx.x;
    const int pw  = tid >> 5;     // 0..6
    const int c8  = tid & 31;     // 0..31

    // rois/img_size are harness inputs (not produced by the transpose):
    // safe to read before the grid dependency resolves.
    const float4 roi = __ldg((const float4*)rois + n);
    const float Hi = __ldg(img_size);
    const float Wi = __ldg(img_size + 1);
    const float sy_scale = (HF - 1.0f) / (Hi - 1.0f);
    const float sx_scale = (WF - 1.0f) / (Wi - 1.0f);
    const float r0 = roi.x * sy_scale;
    const float r1 = roi.y * sx_scale;
    const float h_step = (roi.z * sy_scale - r0) * (1.0f / (float)HS);
    const float w_step = (roi.w * sx_scale - r1) * (1.0f / (float)WS);

    const float yy0 = ((float)(2 * ph) + 0.5f) * h_step + r0;
    const float yy1 = yy0 + h_step;
    const float xx0 = ((float)(2 * pw) + 0.5f) * w_step + r1;
    const float xx1 = xx0 + w_step;

    const int iy0 = __float2int_rd(yy0);
    const int iy1 = __float2int_rd(yy1);
    const int ix0 = __float2int_rd(xx0);
    const int ix1 = __float2int_rd(xx1);

    const __half2 fy0 = __float2half2_rn(yy0 - (float)iy0);
    const __half2 fy1 = __float2half2_rn(yy1 - (float)iy1);
    const __half2 fx0 = __float2half2_rn(xx0 - (float)ix0);
    const __half2 fx1 = __float2half2_rn(xx1 - (float)ix1);

    // corner byte offsets (floor+1 trick: down/right = +stride, weight-0 safe)
    const unsigned ru0 = (unsigned)iy0 * ROW_BYTES;
    const unsigned ru1 = (unsigned)iy1 * ROW_BYTES;
    const unsigned rd0 = ru0 + ROW_BYTES;
    const unsigned rd1 = ru1 + ROW_BYTES;
    const unsigned cl0 = (unsigned)ix0 * COL_BYTES;
    const unsigned cl1 = (unsigned)ix1 * COL_BYTES;
    const unsigned cr0 = cl0 + COL_BYTES;
    const unsigned cr1 = cl1 + COL_BYTES;

    const char* fb = (const char*)g_featTh + c8 * 16;
    const unsigned long long pol = evict_last_policy();

    // writeback indices precomputed in the pre-sync window too
    int wc = tid / 7;
    const int wpw = tid - wc * 7;
    float* gp = out + (size_t)n * (CH * HO * WO) + (size_t)wc * (HO * WO)
                    + ph * WO + wpw;

    // --- wait for the transpose grid's memory to be visible ---
    cudaGridDependencySynchronize();

    // --- 16 forced LDG.128s: 64 live registers, back-to-back issue ---
    unsigned v[64];
    LDG128_NC_EL(v +  0, fb + (ru0 + cl0), pol);   // s0 ul
    LDG128_NC_EL(v +  4, fb + (ru0 + cr0), pol);   // s0 ur
    LDG128_NC_EL(v +  8, fb + (rd0 + cl0), pol);   // s0 dl
    LDG128_NC_EL(v + 12, fb + (rd0 + cr0), pol);   // s0 dr
    LDG128_NC_EL(v + 16, fb + (ru0 + cl1), pol);   // s1 ul
    LDG128_NC_EL(v + 20, fb + (ru0 + cr1), pol);   // s1 ur
    LDG128_NC_EL(v + 24, fb + (rd0 + cl1), pol);   // s1 dl
    LDG128_NC_EL(v + 28, fb + (rd0 + cr1), pol);   // s1 dr
    LDG128_NC_EL(v + 32, fb + (ru1 + cl0), pol);   // s2 ul
    LDG128_NC_EL(v + 36, fb + (ru1 + cr0), pol);   // s2 ur
    LDG128_NC_EL(v + 40, fb + (rd1 + cl0), pol);   // s2 dl
    LDG128_NC_EL(v + 44, fb + (rd1 + cr0), pol);   // s2 dr
    LDG128_NC_EL(v + 48, fb + (ru1 + cl1), pol);   // s3 ul
    LDG128_NC_EL(v + 52, fb + (ru1 + cr1), pol);   // s3 ur
    LDG128_NC_EL(v + 56, fb + (rd1 + cl1), pol);   // s3 dl
    LDG128_NC_EL(v + 60, fb + (rd1 + cr1), pol);   // s3 dr

    __half2 best[4];
    const __half2 ninf = __float2half2_rn(-60000.0f);
#pragma unroll
    for (int j = 0; j < 4; j++) best[j] = ninf;

    const __half2 fxs[4] = {fx0, fx1, fx0, fx1};
    const __half2 fys[4] = {fy0, fy0, fy1, fy1};

#pragma unroll
    for (int s = 0; s < 4; s++) {
        const unsigned* pul = v + s * 16 + 0;
        const unsigned* pur = v + s * 16 + 4;
        const unsigned* pdl = v + s * 16 + 8;
        const unsigned* pdr = v + s * 16 + 12;
        const __half2 fx2 = fxs[s];
        const __half2 fy2 = fys[s];
#pragma unroll
        for (int j = 0; j < 4; j++) {
            const __half2 ul = u2h2(pul[j]);
            const __half2 ur = u2h2(pur[j]);
            const __half2 dl = u2h2(pdl[j]);
            const __half2 dr = u2h2(pdr[j]);
            const __half2 t = __hfma2(fx2, __hsub2(ur, ul), ul);
            const __half2 b = __hfma2(fx2, __hsub2(dr, dl), dl);
            const __half2 vv = __hfma2(fy2, __hsub2(b, t), t);
            best[j] = __hmax2(best[j], vv);
        }
    }

    // --- stage results in fp16 smem ---
    *(uint4*)&s_half[pw * SPITCH + c8 * 8] = *(const uint4*)best;
    __syncthreads();

    // --- writeback: fixed pw per thread, c += 32 per iter ---
    {
        const __half* sp = s_half + wpw * SPITCH;
#pragma unroll
        for (int k = 0; k < 8; k++) {
            *gp = __half2float(sp[wc]);
            wc += 32;
            gp += 32 * (HO * WO);
        }
    }
}

extern "C" void kernel_launch(void* const* d_in, const int* in_sizes, int n_in,
                              void* d_out, int out_size) {
    const float* features = (const float*)d_in[0];  // (1, 256, 200, 200)
    const float* rois     = (const float*)d_in[1];  // (512, 4)
    const float* img_size = (const float*)d_in[2];  // (2,)
    float* out = (float*)d_out;                     // (512, 256, 7, 7)

    const int n_rois = in_sizes[1] / 4;

    dim3 tgrid(HF * WF / 32, CH / 32);
    dim3 tblock(32, 8);
    transpose_kernel<<<tgrid, tblock>>>(features);

    // PDL launch: roialign may begin its prologue before the transpose
    // fully drains; cudaGridDependencySynchronize() gates the featT reads.
    cudaLaunchConfig_t cfg = {};
    cfg.gridDim  = dim3((unsigned)n_rois, HO, 1);
    cfg.blockDim = dim3(NTHR, 1, 1);
    cfg.dynamicSmemBytes = 0;
    cfg.stream = 0;
    cudaLaunchAttribute attrs[1];
    attrs[0].id = cudaLaunchAttributeProgrammaticStreamSerialization;
    attrs[0].val.programmaticStreamSerializationAllowed = 1;
    cfg.attrs = attrs;
    cfg.numAttrs = 1;
    cudaLaunchKernelEx(&cfg, roialign_kernel, rois, img_size, out);
}

// round 17
// speedup vs baseline: 1.3191x; 1.0116x over previous
#include <cuda_runtime.h>
#include <cuda_fp16.h>
#include <math.h>

#define HF 200
#define WF 200
#define CH 256
#define HO 7
#define WO 7
#define SUBS 2
#define HS (HO * SUBS)   // 14
#define WS (WO * SUBS)   // 14

#define ROW_BYTES (WF * CH * 2)   // 102400
#define COL_BYTES (CH * 2)        // 512
#define SPITCH 264                // halves per staged position (256 + 8 pad)
#define NTHR 224

// Channels-last fp16 scratch copy: g_featTh[(y*WF + x)*CH + c]  (20.5 MB)
__device__ __align__(1024) __half g_featTh[HF * WF * CH];

static __device__ __forceinline__ __half2 u2h2(unsigned u) {
    return *reinterpret_cast<__half2*>(&u);
}
static __device__ __forceinline__ unsigned long long evict_last_policy() {
    unsigned long long pol;
    asm("createpolicy.fractional.L2::evict_last.b64 %0, 1.0;" : "=l"(pol));
    return pol;
}

// Forced LDG.128 with L2 evict_last hint: asm outputs can't be register-reused
// by ptxas, so 16 in a row issue back-to-back (MLP = 16 guaranteed).
#define LDG128_NC_EL(r, p, pol)                                                \
    asm volatile("ld.global.nc.L2::cache_hint.v4.u32 {%0,%1,%2,%3}, [%4], %5;" \
                 : "=r"((r)[0]), "=r"((r)[1]), "=r"((r)[2]), "=r"((r)[3])      \
                 : "l"(p), "l"(pol))

// ---------------------------------------------------------------------------
// Kernel 1: transpose (C, H*W) f32 -> (H*W, C) fp16.
// featT stores carry evict_last so the 20.5 MB map stays L2-resident.
// Each block triggers PDL completion on entry so the dependent roialign
// launch can begin its prologue during the transpose tail wave.
// ---------------------------------------------------------------------------
__global__ void transpose_kernel(const float* __restrict__ in) {
    cudaTriggerProgrammaticLaunchCompletion();

    __shared__ float tile[32][33];
    const int p0 = blockIdx.x * 32;
    const int c0 = blockIdx.y * 32;
    const int tx = threadIdx.x;
    const int ty = threadIdx.y;

#pragma unroll
    for (int i = 0; i < 32; i += 8) {
        tile[ty + i][tx] = in[(size_t)(c0 + ty + i) * (HF * WF) + (p0 + tx)];
    }
    __syncthreads();

    const unsigned long long pol = evict_last_policy();
    const int tid = ty * 32 + tx;
#pragma unroll
    for (int it = 0; it < 2; it++) {
        const int idx = tid + it * 256;
        const int p_local = idx >> 4;
        const int k = idx & 15;
        __half2 h = __floats2half2_rn(tile[2 * k][p_local], tile[2 * k + 1][p_local]);
        unsigned hv = *(unsigned*)&h;
        __half* dst = &g_featTh[(size_t)(p0 + p_local) * CH + c0 + 2 * k];
        asm volatile("st.global.L2::cache_hint.b32 [%0], %1, %2;"
                     :: "l"(dst), "r"(hv), "l"(pol) : "memory");
    }
}

// ---------------------------------------------------------------------------
// Kernel 2: ROI align + 2x2 max subsample (proven 24.3us configuration).
// Grid: (N, 7). Block: 224 threads = 7 pw x 32 c8.
// PDL: prologue (geometry, fractions, offsets) runs before
// cudaGridDependencySynchronize(); the forced LDG.128 batch runs after.
// ---------------------------------------------------------------------------
__global__ __launch_bounds__(NTHR, 3) void roialign_kernel(
    const float* __restrict__ rois,
    const float* __restrict__ img_size,
    float* __restrict__ out)
{
    __shared__ __align__(16) __half s_half[WO * SPITCH];  // 3.7 KB

    const int n   = blockIdx.x;
    const int ph  = blockIdx.y;
    const int tid = threadIdx.x;
    const int pw  = tid >> 5;     // 0..6
    const int c8  = tid & 31;     // 0..31

    // rois/img_size are harness inputs (not produced by the transpose):
    // safe to read before the grid dependency resolves.
    const float4 roi = __ldg((const float4*)rois + n);
    const float Hi = __ldg(img_size);
    const float Wi = __ldg(img_size + 1);
    const float sy_scale = (HF - 1.0f) / (Hi - 1.0f);
    const float sx_scale = (WF - 1.0f) / (Wi - 1.0f);
    const float r0 = roi.x * sy_scale;
    const float r1 = roi.y * sx_scale;
    const float h_step = (roi.z * sy_scale - r0) * (1.0f / (float)HS);
    const float w_step = (roi.w * sx_scale - r1) * (1.0f / (float)WS);

    const float yy0 = ((float)(2 * ph) + 0.5f) * h_step + r0;
    const float yy1 = yy0 + h_step;
    const float xx0 = ((float)(2 * pw) + 0.5f) * w_step + r1;
    const float xx1 = xx0 + w_step;

    const int iy0 = __float2int_rd(yy0);
    const int iy1 = __float2int_rd(yy1);
    const int ix0 = __float2int_rd(xx0);
    const int ix1 = __float2int_rd(xx1);

    const __half2 fy0 = __float2half2_rn(yy0 - (float)iy0);
    const __half2 fy1 = __float2half2_rn(yy1 - (float)iy1);
    const __half2 fx0 = __float2half2_rn(xx0 - (float)ix0);
    const __half2 fx1 = __float2half2_rn(xx1 - (float)ix1);

    // corner byte offsets (floor+1 trick: down/right = +stride, weight-0 safe)
    const unsigned ru0 = (unsigned)iy0 * ROW_BYTES;
    const unsigned ru1 = (unsigned)iy1 * ROW_BYTES;
    const unsigned rd0 = ru0 + ROW_BYTES;
    const unsigned rd1 = ru1 + ROW_BYTES;
    const unsigned cl0 = (unsigned)ix0 * COL_BYTES;
    const unsigned cl1 = (unsigned)ix1 * COL_BYTES;
    const unsigned cr0 = cl0 + COL_BYTES;
    const unsigned cr1 = cl1 + COL_BYTES;

    const char* fb = (const char*)g_featTh + c8 * 16;
    const unsigned long long pol = evict_last_policy();

    // writeback indices precomputed in the pre-sync window too
    int wc = tid / 7;
    const int wpw = tid - wc * 7;
    float* gp = out + (size_t)n * (CH * HO * WO) + (size_t)wc * (HO * WO)
                    + ph * WO + wpw;

    // --- wait for the transpose grid's memory to be visible ---
    cudaGridDependencySynchronize();

    // --- 16 forced LDG.128s: 64 live registers, back-to-back issue ---
    unsigned v[64];
    LDG128_NC_EL(v +  0, fb + (ru0 + cl0), pol);   // s0 ul
    LDG128_NC_EL(v +  4, fb + (ru0 + cr0), pol);   // s0 ur
    LDG128_NC_EL(v +  8, fb + (rd0 + cl0), pol);   // s0 dl
    LDG128_NC_EL(v + 12, fb + (rd0 + cr0), pol);   // s0 dr
    LDG128_NC_EL(v + 16, fb + (ru0 + cl1), pol);   // s1 ul
    LDG128_NC_EL(v + 20, fb + (ru0 + cr1), pol);   // s1 ur
    LDG128_NC_EL(v + 24, fb + (rd0 + cl1), pol);   // s1 dl
    LDG128_NC_EL(v + 28, fb + (rd0 + cr1), pol);   // s1 dr
    LDG128_NC_EL(v + 32, fb + (ru1 + cl0), pol);   // s2 ul
    LDG128_NC_EL(v + 36, fb + (ru1 + cr0), pol);   // s2 ur
    LDG128_NC_EL(v + 40, fb + (rd1 + cl0), pol);   // s2 dl
    LDG128_NC_EL(v + 44, fb + (rd1 + cr0), pol);   // s2 dr
    LDG128_NC_EL(v + 48, fb + (ru1 + cl1), pol);   // s3 ul
    LDG128_NC_EL(v + 52, fb + (ru1 + cr1), pol);   // s3 ur
    LDG128_NC_EL(v + 56, fb + (rd1 + cl1), pol);   // s3 dl
    LDG128_NC_EL(v + 60, fb + (rd1 + cr1), pol);   // s3 dr

    __half2 best[4];
    const __half2 ninf = __float2half2_rn(-60000.0f);
#pragma unroll
    for (int j = 0; j < 4; j++) best[j] = ninf;

    const __half2 fxs[4] = {fx0, fx1, fx0, fx1};
    const __half2 fys[4] = {fy0, fy0, fy1, fy1};

#pragma unroll
    for (int s = 0; s < 4; s++) {
        const unsigned* pul = v + s * 16 + 0;
        const unsigned* pur = v + s * 16 + 4;
        const unsigned* pdl = v + s * 16 + 8;
        const unsigned* pdr = v + s * 16 + 12;
        const __half2 fx2 = fxs[s];
        const __half2 fy2 = fys[s];
#pragma unroll
        for (int j = 0; j < 4; j++) {
            const __half2 ul = u2h2(pul[j]);
            const __half2 ur = u2h2(pur[j]);
            const __half2 dl = u2h2(pdl[j]);
            const __half2 dr = u2h2(pdr[j]);
            const __half2 t = __hfma2(fx2, __hsub2(ur, ul), ul);
            const __half2 b = __hfma2(fx2, __hsub2(dr, dl), dl);
            const __half2 vv = __hfma2(fy2, __hsub2(b, t), t);
            best[j] = __hmax2(best[j], vv);
        }
    }

    // --- stage results in fp16 smem ---
    *(uint4*)&s_half[pw * SPITCH + c8 * 8] = *(const uint4*)best;
    __syncthreads();

    // --- writeback: fixed pw per thread, c += 32 per iter ---
    {
        const __half* sp = s_half + wpw * SPITCH;
#pragma unroll
        for (int k = 0; k < 8; k++) {
            *gp = __half2float(sp[wc]);
            wc += 32;
            gp += 32 * (HO * WO);
        }
    }
}

extern "C" void kernel_launch(void* const* d_in, const int* in_sizes, int n_in,
                              void* d_out, int out_size) {
    const float* features = (const float*)d_in[0];  // (1, 256, 200, 200)
    const float* rois     = (const float*)d_in[1];  // (512, 4)
    const float* img_size = (const float*)d_in[2];  // (2,)
    float* out = (float*)d_out;                     // (512, 256, 7, 7)

    const int n_rois = in_sizes[1] / 4;

    dim3 tgrid(HF * WF / 32, CH / 32);
    dim3 tblock(32, 8);
    transpose_kernel<<<tgrid, tblock>>>(features);

    // PDL launch: roialign may begin its prologue before the transpose
    // fully drains; cudaGridDependencySynchronize() gates the featT reads.
    cudaLaunchConfig_t cfg = {};
    cfg.gridDim  = dim3((unsigned)n_rois, HO, 1);
    cfg.blockDim = dim3(NTHR, 1, 1);
    cfg.dynamicSmemBytes = 0;
    cfg.stream = 0;
    cudaLaunchAttribute attrs[1];
    attrs[0].id = cudaLaunchAttributeProgrammaticStreamSerialization;
    attrs[0].val.programmaticStreamSerializationAllowed = 1;
    cfg.attrs = attrs;
    cfg.numAttrs = 1;
    cudaLaunchKernelEx(&cfg, roialign_kernel, rois, img_size, out);
}